// round 16
// baseline (speedup 1.0000x reference)
#include <cuda_runtime.h>
#include <cuda_bf16.h>
#include <math.h>
#include <stdint.h>

#define Bc 128
#define Tc 32
#define Fc 2048
#define G3 6144
#define Hc 64
#define Nn 4096
#define HCTA 256         // scan2 CTAs (2 per SM, 256 <= 2*148 -> co-resident)

// ---- static scratch ----
__device__ float g_Gi[(size_t)Bc*Tc*G3];
__device__ float g_H0[Bc*Tc*Fc];
__device__ float g_Emb[Bc*Tc*Fc];
__device__ float g_XN[Nn*Hc];
__device__ float g_XL[Nn*Hc];
__device__ float g_XR[Nn*Hc];
__device__ float g_G0[Nn*Hc];
__device__ float g_G1[Nn*Hc];
__device__ float g_FUS[Nn*2*Hc];
__device__ float g_PR[(size_t)Nn*2048];

__device__ __nv_bfloat16 g_Xhi[Bc*Tc*Fc],  g_Xlo[Bc*Tc*Fc];
__device__ __nv_bfloat16 g_H0hi[Bc*Tc*Fc], g_H0lo[Bc*Tc*Fc];
__device__ __nv_bfloat16 g_Ehi[Bc*Tc*Fc],  g_Elo[Bc*Tc*Fc];
__device__ __nv_bfloat16 g_hzb[Tc*Fc];
__device__ __nv_bfloat16 g_Wih0h[(size_t)G3*Fc];
__device__ __nv_bfloat16 g_Wih1h[(size_t)G3*Fc];
// Whh PERMUTED u32 (hi only) for scan2: out = (((t*HCTA+c)*3+nt)*64 + lane*2 + s)
__device__ uint32_t g_Whh0h[(size_t)G3*Fc/2];
__device__ uint32_t g_Whh1h[(size_t)G3*Fc/2];

// central barrier state
__device__ unsigned int g_cnt = 0;
__device__ unsigned int g_gen = 0;

// ---- packed f32x2 helpers (capsule GEMM only) ----
__device__ __forceinline__ unsigned long long pk2(float x){
    unsigned long long r; asm("mov.b64 %0,{%1,%1};" : "=l"(r) : "f"(x)); return r;
}
__device__ __forceinline__ void ffma2(unsigned long long& d, unsigned long long a, unsigned long long b){
    asm("fma.rn.f32x2 %0,%1,%2,%0;" : "+l"(d) : "l"(a), "l"(b));
}
__device__ __forceinline__ float2 up2(unsigned long long v){
    float2 r; asm("mov.b64 {%0,%1},%2;" : "=f"(r.x), "=f"(r.y) : "l"(v)); return r;
}

// ---- bf16 mma.sync m16n8k16 ----
__device__ __forceinline__ void mma16816(float* c, uint32_t a0, uint32_t a1, uint32_t a2, uint32_t a3,
                                         uint32_t b0, uint32_t b1){
    asm volatile("mma.sync.aligned.m16n8k16.row.col.f32.bf16.bf16.f32 "
        "{%0,%1,%2,%3}, {%4,%5,%6,%7}, {%8,%9}, {%0,%1,%2,%3};"
        : "+f"(c[0]), "+f"(c[1]), "+f"(c[2]), "+f"(c[3])
        : "r"(a0), "r"(a1), "r"(a2), "r"(a3), "r"(b0), "r"(b1));
}
__device__ __forceinline__ uint32_t ld32(const __nv_bfloat16* p){ return *(const uint32_t*)p; }
__device__ __forceinline__ uint32_t ld32cg(const __nv_bfloat16* p){
    return __ldcg((const unsigned int*)p);
}
__device__ __forceinline__ uint2 ldcg_v2(const uint32_t* p){
    uint2 v; asm volatile("ld.global.cg.v2.u32 {%0,%1}, [%2];" : "=r"(v.x), "=r"(v.y) : "l"(p)); return v;
}

__device__ __forceinline__ void split1(float v, __nv_bfloat16& h, __nv_bfloat16& l){
    h = __float2bfloat16(v);
    l = __float2bfloat16(v - __bfloat162float(h));
}
__device__ __forceinline__ float san1(float v){
    if (isnan(v)) return 0.f;
    if (isinf(v)) return (v>0.f) ? 1.0f : -3.3e38f;
    return v;
}
__device__ __forceinline__ uint32_t packbf2(__nv_bfloat16 a, __nv_bfloat16 b){
    __nv_bfloat162 t; t.x=a; t.y=b; return *(uint32_t*)&t;
}

// ---- fused prep ----
#define SEC0 (Tc*Fc)
#define SEC1 (Bc*Tc*Fc/4)
#define SEC2 ((size_t)G3*Fc/4)
#define SEC3 ((size_t)G3*Fc/4)
#define SEC4 ((size_t)G3*Fc/2)
#define SEC5 ((size_t)G3*Fc/2)
#define PREP_TOT (SEC0+SEC1+SEC2+SEC3+SEC4+SEC5)

__device__ __forceinline__ void wsplit4h_body(const float4* W, __nv_bfloat162* hi, size_t i){
    float4 v = W[i];
    __nv_bfloat162 a,b;
    a.x=__float2bfloat16(v.x); a.y=__float2bfloat16(v.y);
    b.x=__float2bfloat16(v.z); b.y=__float2bfloat16(v.w);
    hi[2*i]=a; hi[2*i+1]=b;
}
// Whh permute for scan2: CTA c owns hidden cols [c*8, c*8+8); n-rows nr = gate*8 + q
__device__ __forceinline__ void wsplitp2_body(const float* W, uint32_t* hi, size_t i){
    int n = (int)(i >> 10);            // W row 0..6143
    int k = ((int)(i & 1023)) << 1;    // even k
    float2 v = *(const float2*)(W + (size_t)n*Fc + k);
    __nv_bfloat16 h0 = __float2bfloat16(v.x);
    __nv_bfloat16 h1 = __float2bfloat16(v.y);
    int g = n >> 11, col = n & 2047;
    int c = col >> 3, q = col & 7;
    int nr = g*8 + q, nt = nr >> 3, gid = nr & 7;
    int t = k >> 4, s = (k >> 3) & 1, tq = (k >> 1) & 3;
    int lane = gid*4 + tq;
    size_t out = (((size_t)t*HCTA + c)*3 + nt)*64 + lane*2 + s;
    hi[out] = packbf2(h0,h1);
}

__global__ void __launch_bounds__(256) k_prep(const float* __restrict__ X,
                                              const float* __restrict__ Wih0, const float* __restrict__ Wih1,
                                              const float* __restrict__ Whh0, const float* __restrict__ Whh1)
{
    size_t i = (size_t)blockIdx.x*256 + threadIdx.x;
    if(i < SEC0){ g_hzb[i]=__float2bfloat16(0.f); return; }
    i -= SEC0;
    if(i < SEC1){
        float4 v = ((const float4*)X)[i];
        v.x=san1(v.x); v.y=san1(v.y); v.z=san1(v.z); v.w=san1(v.w);
        __nv_bfloat16 h0,l0,h1,l1,h2,l2,h3,l3;
        split1(v.x,h0,l0); split1(v.y,h1,l1); split1(v.z,h2,l2); split1(v.w,h3,l3);
        __nv_bfloat162 a,b,c,d; a.x=h0;a.y=h1; b.x=h2;b.y=h3; c.x=l0;c.y=l1; d.x=l2;d.y=l3;
        ((__nv_bfloat162*)g_Xhi)[2*i]=a; ((__nv_bfloat162*)g_Xhi)[2*i+1]=b;
        ((__nv_bfloat162*)g_Xlo)[2*i]=c; ((__nv_bfloat162*)g_Xlo)[2*i+1]=d;
        return;
    }
    i -= SEC1;
    if(i < SEC2){ wsplit4h_body((const float4*)Wih0, (__nv_bfloat162*)g_Wih0h, i); return; }
    i -= SEC2;
    if(i < SEC3){ wsplit4h_body((const float4*)Wih1, (__nv_bfloat162*)g_Wih1h, i); return; }
    i -= SEC3;
    if(i < SEC4){ wsplitp2_body(Whh0, g_Whh0h, i); return; }
    i -= SEC4;
    if(i < SEC5){ wsplitp2_body(Whh1, g_Whh1h, i); return; }
}

__global__ void k_pad(){ if(threadIdx.x == 0) g_cnt = 0u; }

// ---- input-gate GEMM v2 ----
__global__ void __launch_bounds__(128) k_mma2(const __nv_bfloat16* __restrict__ Ahi,
                                              const __nv_bfloat16* __restrict__ Alo,
                                              const __nv_bfloat16* __restrict__ Bhi,
                                              float* __restrict__ Cout,
                                              const float* __restrict__ bias,
                                              int K, int Ncols)
{
    const int lane = threadIdx.x & 31;
    const int warp = threadIdx.x >> 5;
    const int gid = lane >> 2, tq = lane & 3;
    const int m0 = blockIdx.y * 64;
    const int n0 = blockIdx.x * 128 + warp * 32;
    const size_t Ks = K;

    const size_t aoff = (size_t)(m0 + gid)*Ks + tq*2;
    const size_t boff = (size_t)(n0 + gid)*Ks + tq*2;

    float acc[4][4][4];
    #pragma unroll
    for(int mt=0;mt<4;mt++)
        #pragma unroll
        for(int nt=0;nt<4;nt++)
            #pragma unroll
            for(int q=0;q<4;q++) acc[mt][nt][q]=0.f;

    uint32_t ah[4][4], al[4][4], bh[2][4][2];

    {
        const __nv_bfloat16* pb = Bhi + boff;
        bh[0][0][0]=ld32cg(pb);          bh[0][0][1]=ld32cg(pb+8);
        bh[0][1][0]=ld32cg(pb+8*Ks);     bh[0][1][1]=ld32cg(pb+8*Ks+8);
        bh[0][2][0]=ld32cg(pb+16*Ks);    bh[0][2][1]=ld32cg(pb+16*Ks+8);
        bh[0][3][0]=ld32cg(pb+24*Ks);    bh[0][3][1]=ld32cg(pb+24*Ks+8);
    }
    int cur = 0;
    const int NT = K >> 4;
    #pragma unroll 1
    for(int t=0; t<NT; t++){
        if(t+1 < NT){
            const __nv_bfloat16* pb = Bhi + boff + (t+1)*16;
            bh[cur^1][0][0]=ld32cg(pb);          bh[cur^1][0][1]=ld32cg(pb+8);
            bh[cur^1][1][0]=ld32cg(pb+8*Ks);     bh[cur^1][1][1]=ld32cg(pb+8*Ks+8);
            bh[cur^1][2][0]=ld32cg(pb+16*Ks);    bh[cur^1][2][1]=ld32cg(pb+16*Ks+8);
            bh[cur^1][3][0]=ld32cg(pb+24*Ks);    bh[cur^1][3][1]=ld32cg(pb+24*Ks+8);
        }
        const int kb = t*16;
        #pragma unroll
        for(int mt=0;mt<4;mt++){
            const __nv_bfloat16* pa = Ahi + aoff + (size_t)mt*16*Ks + kb;
            const __nv_bfloat16* qa = Alo + aoff + (size_t)mt*16*Ks + kb;
            ah[mt][0]=ld32(pa);        ah[mt][2]=ld32(pa+8);
            ah[mt][1]=ld32(pa+8*Ks);   ah[mt][3]=ld32(pa+8*Ks+8);
            al[mt][0]=ld32(qa);        al[mt][2]=ld32(qa+8);
            al[mt][1]=ld32(qa+8*Ks);   al[mt][3]=ld32(qa+8*Ks+8);
        }
        #pragma unroll
        for(int nt=0;nt<4;nt++){
            #pragma unroll
            for(int mt=0;mt<4;mt++){
                mma16816(acc[mt][nt], ah[mt][0],ah[mt][1],ah[mt][2],ah[mt][3], bh[cur][nt][0], bh[cur][nt][1]);
                mma16816(acc[mt][nt], al[mt][0],al[mt][1],al[mt][2],al[mt][3], bh[cur][nt][0], bh[cur][nt][1]);
            }
        }
        cur ^= 1;
    }

    #pragma unroll
    for(int mt=0;mt<4;mt++){
        #pragma unroll
        for(int nt=0;nt<4;nt++){
            int row = m0 + mt*16 + gid;
            int col = n0 + nt*8 + tq*2;
            float b0 = bias[col], b1 = bias[col+1];
            float2 v0 = {acc[mt][nt][0] + b0, acc[mt][nt][1] + b1};
            float2 v1 = {acc[mt][nt][2] + b0, acc[mt][nt][3] + b1};
            *(float2*)&Cout[(size_t)row*Ncols + col]     = v0;
            *(float2*)&Cout[(size_t)(row+8)*Ncols + col] = v1;
        }
    }
}

// ---- central grid barrier (HCTA arrivals) ----
__device__ __forceinline__ void gbar2(){
    __threadfence();
    __syncthreads();
    if(threadIdx.x==0){
        unsigned int gen = *((volatile unsigned int*)&g_gen);
        if(atomicAdd(&g_cnt, 1u) == HCTA-1u){
            g_cnt = 0;
            __threadfence();
            atomicAdd(&g_gen, 1u);
        } else {
            while(*((volatile unsigned int*)&g_gen) == gen) __nanosleep(40);
        }
        __threadfence();
    }
    __syncthreads();
}

// ---- persistent GRU scan v2b: 256 CTAs (2/SM), CTA owns 8 cols, in-CTA K-reduction ----
__global__ void __launch_bounds__(256, 2) k_scan2(
    const uint32_t* __restrict__ WhiU,
    const float* __restrict__ Gi, const float* __restrict__ bhh,
    const __nv_bfloat16* __restrict__ hzb,
    float* __restrict__ Hall, __nv_bfloat16* __restrict__ Hhi, __nv_bfloat16* __restrict__ Hlo)
{
    __shared__ float sm[8][32][24];   // 24KB
    const int lane = threadIdx.x & 31;
    const int warp = threadIdx.x >> 5;      // 0..7 (K chunk)
    const int gid = lane >> 2, tq = lane & 3;
    const int c = blockIdx.x;
    const int jc = c*8;
    const size_t Ks = Fc;
    const int kw = warp*256;
    const int T0 = warp*16;
    const size_t aoff = (size_t)gid*Ks + tq*2;

    for(int b=0; b<Bc; b++){
        const __nv_bfloat16* Ahi = b ? (Hhi + (size_t)(b-1)*Tc*Fc) : hzb;
        const __nv_bfloat16* Alo = b ? (Hlo + (size_t)(b-1)*Tc*Fc) : hzb;

        // ---- GEMM: 32 x 24 x 256 per warp, 2-term ----
        float acc[2][3][4];
        #pragma unroll
        for(int mt=0;mt<2;mt++)
            #pragma unroll
            for(int nt=0;nt<3;nt++)
                #pragma unroll
                for(int q=0;q<4;q++) acc[mt][nt][q]=0.f;

        uint32_t ah[2][4], al[2][4], bh[2][3][2];
        {
            const size_t bo = (((size_t)T0*HCTA + c)*3)*64 + lane*2;
            #pragma unroll
            for(int nn=0;nn<3;nn++){
                uint2 u = ldcg_v2(WhiU + bo + nn*64);
                bh[0][nn][0]=u.x; bh[0][nn][1]=u.y;
            }
        }
        int cur = 0;
        #pragma unroll 1
        for(int t=0; t<16; t++){
            if(t+1 < 16){
                const size_t bo = (((size_t)(T0+t+1)*HCTA + c)*3)*64 + lane*2;
                #pragma unroll
                for(int nn=0;nn<3;nn++){
                    uint2 u = ldcg_v2(WhiU + bo + nn*64);
                    bh[cur^1][nn][0]=u.x; bh[cur^1][nn][1]=u.y;
                }
            }
            const int kb = kw + t*16;
            const __nv_bfloat16 *pa = Ahi + aoff + kb;
            const __nv_bfloat16 *qa = Alo + aoff + kb;
            ah[0][0]=ld32(pa);        ah[0][2]=ld32(pa+8);
            ah[0][1]=ld32(pa+8*Ks);   ah[0][3]=ld32(pa+8*Ks+8);
            ah[1][0]=ld32(pa+16*Ks);  ah[1][2]=ld32(pa+16*Ks+8);
            ah[1][1]=ld32(pa+24*Ks);  ah[1][3]=ld32(pa+24*Ks+8);
            al[0][0]=ld32(qa);        al[0][2]=ld32(qa+8);
            al[0][1]=ld32(qa+8*Ks);   al[0][3]=ld32(qa+8*Ks+8);
            al[1][0]=ld32(qa+16*Ks);  al[1][2]=ld32(qa+16*Ks+8);
            al[1][1]=ld32(qa+24*Ks);  al[1][3]=ld32(qa+24*Ks+8);
            #pragma unroll
            for(int nn=0;nn<3;nn++){
                #pragma unroll
                for(int mt=0;mt<2;mt++){
                    mma16816(acc[mt][nn], ah[mt][0],ah[mt][1],ah[mt][2],ah[mt][3], bh[cur][nn][0], bh[cur][nn][1]);
                    mma16816(acc[mt][nn], al[mt][0],al[mt][1],al[mt][2],al[mt][3], bh[cur][nn][0], bh[cur][nn][1]);
                }
            }
            cur ^= 1;
        }

        // deposit partial 32x24 tile to smem
        #pragma unroll
        for(int mt=0;mt<2;mt++){
            #pragma unroll
            for(int nn=0;nn<3;nn++){
                int row = mt*16 + gid;
                int col = nn*8 + tq*2;
                *(float2*)&sm[warp][row][col]   = *(float2*)&acc[mt][nn][0];
                *(float2*)&sm[warp][row+8][col] = *(float2*)&acc[mt][nn][2];
            }
        }
        __syncthreads();

        // ---- reduce over 8 warps + gate; 1 output per thread (256 = 32 rows x 8 cols) ----
        {
            int o = threadIdx.x;
            int row = o >> 3, q = o & 7;
            float gr=0.f, gz=0.f, gn=0.f;
            #pragma unroll
            for(int w=0;w<8;w++){
                gr += sm[w][row][q];
                gz += sm[w][row][8+q];
                gn += sm[w][row][16+q];
            }
            int j = jc + q;
            const float* gi = Gi + ((size_t)b*Tc + row)*G3;
            float r = 1.f/(1.f + expf(-(gi[j]      + gr + bhh[j])));
            float z = 1.f/(1.f + expf(-(gi[2048+j] + gz + bhh[2048+j])));
            float n = tanhf(gi[4096+j] + r*(gn + bhh[4096+j]));
            float hpv = b ? Hall[((size_t)(b-1)*Tc + row)*Fc + j] : 0.f;
            float h = (1.f - z)*n + z*hpv;
            size_t base = ((size_t)b*Tc + row)*Fc + j;
            Hall[base] = h;
            __nv_bfloat16 hh, hl;
            split1(h, hh, hl);
            Hhi[base] = hh;
            Hlo[base] = hl;
        }
        gbar2();   // h(b) fully visible; also protects smem reuse
    }
}

// ---- f32 SGEMM (capsule priors only) ----
__global__ void __launch_bounds__(256) k_sgemm(const float* __restrict__ A,
                                               const float* __restrict__ Bm,
                                               const float* __restrict__ bias,
                                               float* __restrict__ C,
                                               int Ncols, int K)
{
    __shared__ float As[8][128];
    __shared__ float Bs[8][128];
    const int tid = threadIdx.x;
    const int tx = tid & 15, ty = tid >> 4;
    const int m0 = blockIdx.y*128, n0 = blockIdx.x*128;
    const int lr = tid >> 1, lc = (tid & 1)*4;
    const float* Ap = A + (size_t)(m0+lr)*K + lc;
    const float* Bp = Bm + (size_t)(n0+lr)*K + lc;

    unsigned long long acc[8][4];
    #pragma unroll
    for(int i=0;i<8;i++)
        #pragma unroll
        for(int j=0;j<4;j++) acc[i][j]=0ULL;

    for(int k0=0;k0<K;k0+=8){
        float4 av = *(const float4*)(Ap + k0);
        float4 bv = *(const float4*)(Bp + k0);
        __syncthreads();
        As[lc+0][lr]=av.x; As[lc+1][lr]=av.y; As[lc+2][lr]=av.z; As[lc+3][lr]=av.w;
        Bs[lc+0][lr]=bv.x; Bs[lc+1][lr]=bv.y; Bs[lc+2][lr]=bv.z; Bs[lc+3][lr]=bv.w;
        __syncthreads();
        #pragma unroll
        for(int k=0;k<8;k++){
            float4 a0 = *(const float4*)&As[k][ty*8];
            float4 a1 = *(const float4*)&As[k][ty*8+4];
            ulonglong2 b01 = *(const ulonglong2*)&Bs[k][tx*8];
            ulonglong2 b23 = *(const ulonglong2*)&Bs[k][tx*8+4];
            unsigned long long aa[8];
            aa[0]=pk2(a0.x); aa[1]=pk2(a0.y); aa[2]=pk2(a0.z); aa[3]=pk2(a0.w);
            aa[4]=pk2(a1.x); aa[5]=pk2(a1.y); aa[6]=pk2(a1.z); aa[7]=pk2(a1.w);
            #pragma unroll
            for(int i=0;i<8;i++){
                ffma2(acc[i][0], aa[i], b01.x);
                ffma2(acc[i][1], aa[i], b01.y);
                ffma2(acc[i][2], aa[i], b23.x);
                ffma2(acc[i][3], aa[i], b23.y);
            }
        }
    }
    #pragma unroll
    for(int i=0;i<8;i++){
        int row = m0 + ty*8 + i;
        #pragma unroll
        for(int j=0;j<4;j++){
            float2 v = up2(acc[i][j]);
            int col = n0 + tx*8 + j*2;
            float b0 = bias ? bias[col]   : 0.f;
            float b1 = bias ? bias[col+1] : 0.f;
            C[(size_t)row*Ncols + col]   = v.x + b0;
            C[(size_t)row*Ncols + col+1] = v.y + b1;
        }
    }
}

// ---- temporal attention ----
__global__ void __launch_bounds__(256) k_attn(const float* __restrict__ Emb,
                                              const float* __restrict__ Aw,
                                              const float* __restrict__ Ab,
                                              float* __restrict__ XN)
{
    __shared__ float sW[32][33];
    __shared__ float sB[32];
    int tid = threadIdx.x;
    for(int i=tid;i<1024;i+=256) sW[i>>5][i&31] = Aw[i];
    if(tid<32) sB[tid]=Ab[tid];
    __syncthreads();
    int g = blockIdx.x*256 + tid;
    int b = g >> 11, f = g & 2047;
    float tA[32];
    #pragma unroll
    for(int t=0;t<32;t++) tA[t] = tanhf(Emb[((size_t)b*32 + t)*Fc + f]);
    float mx = -1e30f, aw[32];
    #pragma unroll
    for(int t2=0;t2<32;t2++){
        float s = sB[t2];
        #pragma unroll
        for(int t=0;t<32;t++) s += tA[t]*sW[t2][t];
        aw[t2]=s; mx = fmaxf(mx, s);
    }
    float den=0.f, num=0.f;
    #pragma unroll
    for(int t=0;t<32;t++){ float e = expf(aw[t]-mx); den += e; num += e*tA[t]; }
    XN[g] = tanhf(num/den);
}

// ---- GAT projections ----
__global__ void __launch_bounds__(256) k_lin64(const float* __restrict__ X,
                                               const float* __restrict__ Wl, const float* __restrict__ bl,
                                               const float* __restrict__ Wr, const float* __restrict__ br,
                                               float* __restrict__ XL, float* __restrict__ XR)
{
    __shared__ float sX[64][65];
    __shared__ float sW[64][65];
    int tid = threadIdx.x;
    int r0 = blockIdx.x*64;
    for(int i=tid;i<4096;i+=256){ int r=i>>6, c=i&63; sX[r][c]=X[(size_t)(r0+r)*64+c]; }
    for(int i=tid;i<4096;i+=256){ int r=i>>6, c=i&63; sW[r][c]=Wl[i]; }
    __syncthreads();
    int r = tid & 63, cq = tid >> 6;
    #pragma unroll 4
    for(int cc=0; cc<16; cc++){
        int c = cq*16 + cc;
        float s = bl[c];
        #pragma unroll
        for(int k=0;k<64;k++) s += sX[r][k]*sW[c][k];
        XL[(size_t)(r0+r)*64 + c] = s;
    }
    __syncthreads();
    for(int i=tid;i<4096;i+=256){ int rr=i>>6, c=i&63; sW[rr][c]=Wr[i]; }
    __syncthreads();
    #pragma unroll 4
    for(int cc=0; cc<16; cc++){
        int c = cq*16 + cc;
        float s = br[c];
        #pragma unroll
        for(int k=0;k<64;k++) s += sX[r][k]*sW[c][k];
        XR[(size_t)(r0+r)*64 + c] = s;
    }
}

// ---- GATv2 dense 32x32 block graph ----
__global__ void __launch_bounds__(128) k_gat(const float* __restrict__ XL,
                                             const float* __restrict__ XR,
                                             const float* __restrict__ att,
                                             const float* __restrict__ bias,
                                             float* __restrict__ OUT)
{
    int w = threadIdx.x >> 5, lane = threadIdx.x & 31;
    int g = blockIdx.x >> 3;
    int d = ((blockIdx.x & 7) << 2) + w;
    int nd = g*32 + d;
    float xr0 = XR[(size_t)nd*64 + lane];
    float xr1 = XR[(size_t)nd*64 + 32 + lane];
    float a0 = att[lane], a1 = att[lane+32];
    const float* xlg = XL + (size_t)g*32*64;
    float lg[32];
    #pragma unroll
    for(int s=0;s<32;s++){
        float u = xlg[s*64 + lane]      + xr0;
        float v = xlg[s*64 + 32 + lane] + xr1;
        u = u>0.f ? u : 0.2f*u;
        v = v>0.f ? v : 0.2f*v;
        float t = u*a0 + v*a1;
        #pragma unroll
        for(int o=16;o>0;o>>=1) t += __shfl_xor_sync(0xffffffffu, t, o);
        lg[s] = t;
    }
    float m = -1e30f;
    #pragma unroll
    for(int s=0;s<32;s++) m = fmaxf(m, lg[s]);
    float den = 0.f;
    #pragma unroll
    for(int s=0;s<32;s++){ lg[s] = expf(lg[s]-m); den += lg[s]; }
    float inv = 1.f/den, o0=0.f, o1=0.f;
    #pragma unroll
    for(int s=0;s<32;s++){
        float al = lg[s]*inv;
        o0 += al * xlg[s*64 + lane];
        o1 += al * xlg[s*64 + 32 + lane];
    }
    OUT[(size_t)nd*64 + lane]      = tanhf(o0 + bias[lane]);
    OUT[(size_t)nd*64 + 32 + lane] = tanhf(o1 + bias[lane+32]);
}

// ---- fusion concat ----
__global__ void k_fus(const float* __restrict__ XN, const float* __restrict__ G0,
                      const float* __restrict__ G1, float* __restrict__ FUS)
{
    int i = blockIdx.x*256 + threadIdx.x;
    int n = i >> 7, q = i & 127;
    FUS[i] = (q < 64) ? XN[(size_t)n*64 + q]
                      : (G0[(size_t)n*64 + q-64] + G1[(size_t)n*64 + q-64]);
}

// ---- capsule routing + head ----
__global__ void __launch_bounds__(64) k_route(const float* __restrict__ PR,
                                              const float* __restrict__ Fw,
                                              const float* __restrict__ Fb,
                                              float* __restrict__ out)
{
    int n = blockIdx.x, l = threadIdx.x;
    const float* base = PR + (size_t)n*65536 + l;
    float o0[32], o1[32], pc[32], te[32];
    #pragma unroll
    for(int o=0;o<32;o++) o0[o]=0.f;
    for(int c=0;c<32;c++){
        const float* pcol = base + (size_t)c*2048;
        #pragma unroll
        for(int o=0;o<32;o++) o0[o] += pcol[o*64];
    }
    #pragma unroll
    for(int o=0;o<32;o++){ o0[o] *= (1.f/32.f); o1[o]=0.f; }
    for(int c=0;c<32;c++){
        const float* pcol = base + (size_t)c*2048;
        float m = -1e30f;
        #pragma unroll
        for(int o=0;o<32;o++){ pc[o]=pcol[o*64]; float lgv = pc[o]*o0[o]; te[o]=lgv; m = fmaxf(m,lgv); }
        float den=0.f;
        #pragma unroll
        for(int o=0;o<32;o++){ te[o]=expf(te[o]-m); den+=te[o]; }
        float inv = 1.f/den;
        #pragma unroll
        for(int o=0;o<32;o++) o1[o] += te[o]*inv*pc[o];
    }
    #pragma unroll
    for(int o=0;o<32;o++){ o0[o] += o1[o]; o1[o]=0.f; }
    for(int c=0;c<32;c++){
        const float* pcol = base + (size_t)c*2048;
        float m = -1e30f;
        #pragma unroll
        for(int o=0;o<32;o++){ pc[o]=pcol[o*64]; float lgv = pc[o]*o0[o]; te[o]=lgv; m = fmaxf(m,lgv); }
        float den=0.f;
        #pragma unroll
        for(int o=0;o<32;o++){ te[o]=expf(te[o]-m); den+=te[o]; }
        float inv = 1.f/den;
        #pragma unroll
        for(int o=0;o<32;o++) o1[o] += te[o]*inv*pc[o];
    }
    __shared__ float sc[32][65];
    #pragma unroll
    for(int o=0;o<32;o++) sc[o][l] = tanhf(o1[o]);
    __syncthreads();
    for(int q=0;q<16;q++){
        int idx = l*16 + q;
        int o = idx >> 5, d2 = idx & 31;
        float s = Fb[d2];
        #pragma unroll
        for(int ll=0;ll<64;ll++) s += sc[o][ll]*Fw[d2*64+ll];
        out[(size_t)n*1024 + o*32 + d2] = tanhf(s);
    }
}

extern "C" void kernel_launch(void* const* d_in, const int* in_sizes, int n_in,
                              void* d_out, int out_size)
{
    const float* inputs = (const float*)d_in[0];
    const float* Wih0 = (const float*)d_in[1];
    const float* Whh0 = (const float*)d_in[2];
    const float* bih0 = (const float*)d_in[3];
    const float* bhh0 = (const float*)d_in[4];
    const float* Wih1 = (const float*)d_in[5];
    const float* Whh1 = (const float*)d_in[6];
    const float* bih1 = (const float*)d_in[7];
    const float* bhh1 = (const float*)d_in[8];
    const float* A_w  = (const float*)d_in[9];
    const float* A_b  = (const float*)d_in[10];
    const float* g0_Wl = (const float*)d_in[11];
    const float* g0_bl = (const float*)d_in[12];
    const float* g0_Wr = (const float*)d_in[13];
    const float* g0_br = (const float*)d_in[14];
    const float* g0_att = (const float*)d_in[15];
    const float* g0_bias = (const float*)d_in[16];
    const float* g1_Wl = (const float*)d_in[17];
    const float* g1_bl = (const float*)d_in[18];
    const float* g1_Wr = (const float*)d_in[19];
    const float* g1_br = (const float*)d_in[20];
    const float* g1_att = (const float*)d_in[21];
    const float* g1_bias = (const float*)d_in[22];
    const float* W_caps = (const float*)d_in[23];
    const float* F_w = (const float*)d_in[24];
    const float* F_b = (const float*)d_in[25];
    float* out = (float*)d_out;

    float *Gi,*H0,*Emb,*XN,*XL,*XR,*G0,*G1,*FUS,*PR;
    __nv_bfloat16 *Xhi,*Xlo,*H0hi,*H0lo,*Ehi,*Elo,*hzb;
    __nv_bfloat16 *Wih0h,*Wih1h;
    uint32_t *Whh0hU,*Whh1hU;
    cudaGetSymbolAddress((void**)&Gi,  g_Gi);
    cudaGetSymbolAddress((void**)&H0,  g_H0);
    cudaGetSymbolAddress((void**)&Emb, g_Emb);
    cudaGetSymbolAddress((void**)&XN,  g_XN);
    cudaGetSymbolAddress((void**)&XL,  g_XL);
    cudaGetSymbolAddress((void**)&XR,  g_XR);
    cudaGetSymbolAddress((void**)&G0,  g_G0);
    cudaGetSymbolAddress((void**)&G1,  g_G1);
    cudaGetSymbolAddress((void**)&FUS, g_FUS);
    cudaGetSymbolAddress((void**)&PR,  g_PR);
    cudaGetSymbolAddress((void**)&Xhi, g_Xhi);  cudaGetSymbolAddress((void**)&Xlo, g_Xlo);
    cudaGetSymbolAddress((void**)&H0hi,g_H0hi); cudaGetSymbolAddress((void**)&H0lo,g_H0lo);
    cudaGetSymbolAddress((void**)&Ehi, g_Ehi);  cudaGetSymbolAddress((void**)&Elo, g_Elo);
    cudaGetSymbolAddress((void**)&hzb, g_hzb);
    cudaGetSymbolAddress((void**)&Wih0h, g_Wih0h);
    cudaGetSymbolAddress((void**)&Wih1h, g_Wih1h);
    cudaGetSymbolAddress((void**)&Whh0hU, g_Whh0h);
    cudaGetSymbolAddress((void**)&Whh1hU, g_Whh1h);

    // launch order (profiler index = mine + 2): 0 prep, 1 mma2, 2 pad, 3 scan2 L0 <- ncu slot 5
    const size_t prep_ctas = (PREP_TOT + 255) / 256;
    k_prep<<<(unsigned)prep_ctas, 256>>>(inputs, Wih0, Wih1, Whh0, Whh1);
    k_mma2<<<dim3(G3/128, (Bc*Tc)/64), 128>>>(Xhi, Xlo, Wih0h, Gi, bih0, Fc, G3);
    k_pad<<<1, 32>>>();
    k_scan2<<<HCTA, 256>>>(Whh0hU, Gi, bhh0, hzb, H0, H0hi, H0lo);
    k_mma2<<<dim3(G3/128, (Bc*Tc)/64), 128>>>(H0hi, H0lo, Wih1h, Gi, bih1, Fc, G3);
    k_scan2<<<HCTA, 256>>>(Whh1hU, Gi, bhh1, hzb, Emb, Ehi, Elo);
    // attention -> node features
    k_attn<<<(Bc*Fc)/256, 256>>>(Emb, A_w, A_b, XN);
    // GAT layers
    k_lin64<<<Nn/64, 256>>>(XN, g0_Wl, g0_bl, g0_Wr, g0_br, XL, XR);
    k_gat<<<1024, 128>>>(XL, XR, g0_att, g0_bias, G0);
    k_lin64<<<Nn/64, 256>>>(G0, g1_Wl, g1_bl, g1_Wr, g1_br, XL, XR);
    k_gat<<<1024, 128>>>(XL, XR, g1_att, g1_bias, G1);
    // fusion + capsule priors
    k_fus<<<(Nn*128)/256, 256>>>(XN, G0, G1, FUS);
    k_sgemm<<<dim3(2048/128, Nn/128), 256>>>(FUS, W_caps, nullptr, PR, 2048, 128);
    // routing + head
    k_route<<<Bc, 64>>>(PR, F_w, F_b, out);
}

// round 17
// speedup vs baseline: 1.2444x; 1.2444x over previous
#include <cuda_runtime.h>
#include <cuda_bf16.h>
#include <math.h>
#include <stdint.h>

#define Bc 128
#define Tc 32
#define Fc 2048
#define G3 6144
#define Hc 64
#define Nn 4096
#define HCTA 128         // scan2 CTAs (1 per SM)

// ---- static scratch ----
__device__ float g_Gi[(size_t)Bc*Tc*G3];
__device__ float g_H0[Bc*Tc*Fc];
__device__ float g_Emb[Bc*Tc*Fc];
__device__ float g_XN[Nn*Hc];
__device__ float g_XL[Nn*Hc];
__device__ float g_XR[Nn*Hc];
__device__ float g_G0[Nn*Hc];
__device__ float g_G1[Nn*Hc];
__device__ float g_FUS[Nn*2*Hc];
__device__ float g_PR[(size_t)Nn*2048];

__device__ __nv_bfloat16 g_Xhi[Bc*Tc*Fc],  g_Xlo[Bc*Tc*Fc];
__device__ __nv_bfloat16 g_H0hi[Bc*Tc*Fc], g_H0lo[Bc*Tc*Fc];
__device__ __nv_bfloat16 g_Ehi[Bc*Tc*Fc],  g_Elo[Bc*Tc*Fc];
__device__ __nv_bfloat16 g_hzb[Tc*Fc];
__device__ __nv_bfloat16 g_Wih0h[(size_t)G3*Fc];
__device__ __nv_bfloat16 g_Wih1h[(size_t)G3*Fc];
// Whh PERMUTED u32 (hi only): out = (((t*HCTA+c)*6+nt)*64 + lane*2 + s), t=global ktile
__device__ uint32_t g_Whh0h[(size_t)G3*Fc/2];
__device__ uint32_t g_Whh1h[(size_t)G3*Fc/2];

// central barrier state
__device__ unsigned int g_cnt = 0;
__device__ unsigned int g_gen = 0;

// ---- packed f32x2 helpers (capsule GEMM only) ----
__device__ __forceinline__ unsigned long long pk2(float x){
    unsigned long long r; asm("mov.b64 %0,{%1,%1};" : "=l"(r) : "f"(x)); return r;
}
__device__ __forceinline__ void ffma2(unsigned long long& d, unsigned long long a, unsigned long long b){
    asm("fma.rn.f32x2 %0,%1,%2,%0;" : "+l"(d) : "l"(a), "l"(b));
}
__device__ __forceinline__ float2 up2(unsigned long long v){
    float2 r; asm("mov.b64 {%0,%1},%2;" : "=f"(r.x), "=f"(r.y) : "l"(v)); return r;
}

// ---- bf16 mma.sync m16n8k16 ----
__device__ __forceinline__ void mma16816(float* c, uint32_t a0, uint32_t a1, uint32_t a2, uint32_t a3,
                                         uint32_t b0, uint32_t b1){
    asm volatile("mma.sync.aligned.m16n8k16.row.col.f32.bf16.bf16.f32 "
        "{%0,%1,%2,%3}, {%4,%5,%6,%7}, {%8,%9}, {%0,%1,%2,%3};"
        : "+f"(c[0]), "+f"(c[1]), "+f"(c[2]), "+f"(c[3])
        : "r"(a0), "r"(a1), "r"(a2), "r"(a3), "r"(b0), "r"(b1));
}
__device__ __forceinline__ uint32_t ld32(const __nv_bfloat16* p){ return *(const uint32_t*)p; }
__device__ __forceinline__ uint32_t ld32cg(const __nv_bfloat16* p){
    return __ldcg((const unsigned int*)p);
}
__device__ __forceinline__ uint2 ldcg_v2(const uint32_t* p){
    uint2 v; asm volatile("ld.global.cg.v2.u32 {%0,%1}, [%2];" : "=r"(v.x), "=r"(v.y) : "l"(p)); return v;
}

__device__ __forceinline__ void split1(float v, __nv_bfloat16& h, __nv_bfloat16& l){
    h = __float2bfloat16(v);
    l = __float2bfloat16(v - __bfloat162float(h));
}
__device__ __forceinline__ float san1(float v){
    if (isnan(v)) return 0.f;
    if (isinf(v)) return (v>0.f) ? 1.0f : -3.3e38f;
    return v;
}
__device__ __forceinline__ uint32_t packbf2(__nv_bfloat16 a, __nv_bfloat16 b){
    __nv_bfloat162 t; t.x=a; t.y=b; return *(uint32_t*)&t;
}

// ---- fused prep ----
#define SEC0 (Tc*Fc)
#define SEC1 (Bc*Tc*Fc/4)
#define SEC2 ((size_t)G3*Fc/4)
#define SEC3 ((size_t)G3*Fc/4)
#define SEC4 ((size_t)G3*Fc/2)
#define SEC5 ((size_t)G3*Fc/2)
#define PREP_TOT (SEC0+SEC1+SEC2+SEC3+SEC4+SEC5)

__device__ __forceinline__ void wsplit4h_body(const float4* W, __nv_bfloat162* hi, size_t i){
    float4 v = W[i];
    __nv_bfloat162 a,b;
    a.x=__float2bfloat16(v.x); a.y=__float2bfloat16(v.y);
    b.x=__float2bfloat16(v.z); b.y=__float2bfloat16(v.w);
    hi[2*i]=a; hi[2*i+1]=b;
}
// Whh permute: CTA c owns hidden cols [c*16, c*16+16); n-rows nr = gate*16 + q
__device__ __forceinline__ void wsplitp2_body(const float* W, uint32_t* hi, size_t i){
    int n = (int)(i >> 10);            // W row 0..6143
    int k = ((int)(i & 1023)) << 1;    // even k
    float2 v = *(const float2*)(W + (size_t)n*Fc + k);
    __nv_bfloat16 h0 = __float2bfloat16(v.x);
    __nv_bfloat16 h1 = __float2bfloat16(v.y);
    int g = n >> 11, col = n & 2047;
    int c = col >> 4, q = col & 15;
    int nr = g*16 + q, nt = nr >> 3, gid = nr & 7;
    int t = k >> 4, s = (k >> 3) & 1, tq = (k >> 1) & 3;
    int lane = gid*4 + tq;
    size_t out = (((size_t)t*HCTA + c)*6 + nt)*64 + lane*2 + s;
    hi[out] = packbf2(h0,h1);
}

__global__ void __launch_bounds__(256) k_prep(const float* __restrict__ X,
                                              const float* __restrict__ Wih0, const float* __restrict__ Wih1,
                                              const float* __restrict__ Whh0, const float* __restrict__ Whh1)
{
    size_t i = (size_t)blockIdx.x*256 + threadIdx.x;
    if(i < SEC0){ g_hzb[i]=__float2bfloat16(0.f); return; }
    i -= SEC0;
    if(i < SEC1){
        float4 v = ((const float4*)X)[i];
        v.x=san1(v.x); v.y=san1(v.y); v.z=san1(v.z); v.w=san1(v.w);
        __nv_bfloat16 h0,l0,h1,l1,h2,l2,h3,l3;
        split1(v.x,h0,l0); split1(v.y,h1,l1); split1(v.z,h2,l2); split1(v.w,h3,l3);
        __nv_bfloat162 a,b,c,d; a.x=h0;a.y=h1; b.x=h2;b.y=h3; c.x=l0;c.y=l1; d.x=l2;d.y=l3;
        ((__nv_bfloat162*)g_Xhi)[2*i]=a; ((__nv_bfloat162*)g_Xhi)[2*i+1]=b;
        ((__nv_bfloat162*)g_Xlo)[2*i]=c; ((__nv_bfloat162*)g_Xlo)[2*i+1]=d;
        return;
    }
    i -= SEC1;
    if(i < SEC2){ wsplit4h_body((const float4*)Wih0, (__nv_bfloat162*)g_Wih0h, i); return; }
    i -= SEC2;
    if(i < SEC3){ wsplit4h_body((const float4*)Wih1, (__nv_bfloat162*)g_Wih1h, i); return; }
    i -= SEC3;
    if(i < SEC4){ wsplitp2_body(Whh0, g_Whh0h, i); return; }
    i -= SEC4;
    if(i < SEC5){ wsplitp2_body(Whh1, g_Whh1h, i); return; }
}

__global__ void k_pad(){ if(threadIdx.x == 0) g_cnt = 0u; }

// ---- input-gate GEMM v2 ----
__global__ void __launch_bounds__(128) k_mma2(const __nv_bfloat16* __restrict__ Ahi,
                                              const __nv_bfloat16* __restrict__ Alo,
                                              const __nv_bfloat16* __restrict__ Bhi,
                                              float* __restrict__ Cout,
                                              const float* __restrict__ bias,
                                              int K, int Ncols)
{
    const int lane = threadIdx.x & 31;
    const int warp = threadIdx.x >> 5;
    const int gid = lane >> 2, tq = lane & 3;
    const int m0 = blockIdx.y * 64;
    const int n0 = blockIdx.x * 128 + warp * 32;
    const size_t Ks = K;

    const size_t aoff = (size_t)(m0 + gid)*Ks + tq*2;
    const size_t boff = (size_t)(n0 + gid)*Ks + tq*2;

    float acc[4][4][4];
    #pragma unroll
    for(int mt=0;mt<4;mt++)
        #pragma unroll
        for(int nt=0;nt<4;nt++)
            #pragma unroll
            for(int q=0;q<4;q++) acc[mt][nt][q]=0.f;

    uint32_t ah[4][4], al[4][4], bh[2][4][2];

    {
        const __nv_bfloat16* pb = Bhi + boff;
        bh[0][0][0]=ld32cg(pb);          bh[0][0][1]=ld32cg(pb+8);
        bh[0][1][0]=ld32cg(pb+8*Ks);     bh[0][1][1]=ld32cg(pb+8*Ks+8);
        bh[0][2][0]=ld32cg(pb+16*Ks);    bh[0][2][1]=ld32cg(pb+16*Ks+8);
        bh[0][3][0]=ld32cg(pb+24*Ks);    bh[0][3][1]=ld32cg(pb+24*Ks+8);
    }
    int cur = 0;
    const int NT = K >> 4;
    #pragma unroll 1
    for(int t=0; t<NT; t++){
        if(t+1 < NT){
            const __nv_bfloat16* pb = Bhi + boff + (t+1)*16;
            bh[cur^1][0][0]=ld32cg(pb);          bh[cur^1][0][1]=ld32cg(pb+8);
            bh[cur^1][1][0]=ld32cg(pb+8*Ks);     bh[cur^1][1][1]=ld32cg(pb+8*Ks+8);
            bh[cur^1][2][0]=ld32cg(pb+16*Ks);    bh[cur^1][2][1]=ld32cg(pb+16*Ks+8);
            bh[cur^1][3][0]=ld32cg(pb+24*Ks);    bh[cur^1][3][1]=ld32cg(pb+24*Ks+8);
        }
        const int kb = t*16;
        #pragma unroll
        for(int mt=0;mt<4;mt++){
            const __nv_bfloat16* pa = Ahi + aoff + (size_t)mt*16*Ks + kb;
            const __nv_bfloat16* qa = Alo + aoff + (size_t)mt*16*Ks + kb;
            ah[mt][0]=ld32(pa);        ah[mt][2]=ld32(pa+8);
            ah[mt][1]=ld32(pa+8*Ks);   ah[mt][3]=ld32(pa+8*Ks+8);
            al[mt][0]=ld32(qa);        al[mt][2]=ld32(qa+8);
            al[mt][1]=ld32(qa+8*Ks);   al[mt][3]=ld32(qa+8*Ks+8);
        }
        #pragma unroll
        for(int nt=0;nt<4;nt++){
            #pragma unroll
            for(int mt=0;mt<4;mt++){
                mma16816(acc[mt][nt], ah[mt][0],ah[mt][1],ah[mt][2],ah[mt][3], bh[cur][nt][0], bh[cur][nt][1]);
                mma16816(acc[mt][nt], al[mt][0],al[mt][1],al[mt][2],al[mt][3], bh[cur][nt][0], bh[cur][nt][1]);
            }
        }
        cur ^= 1;
    }

    #pragma unroll
    for(int mt=0;mt<4;mt++){
        #pragma unroll
        for(int nt=0;nt<4;nt++){
            int row = m0 + mt*16 + gid;
            int col = n0 + nt*8 + tq*2;
            float b0 = bias[col], b1 = bias[col+1];
            float2 v0 = {acc[mt][nt][0] + b0, acc[mt][nt][1] + b1};
            float2 v1 = {acc[mt][nt][2] + b0, acc[mt][nt][3] + b1};
            *(float2*)&Cout[(size_t)row*Ncols + col]     = v0;
            *(float2*)&Cout[(size_t)(row+8)*Ncols + col] = v1;
        }
    }
}

// ---- central grid barrier (HCTA arrivals) ----
__device__ __forceinline__ void gbar2(){
    __threadfence();
    __syncthreads();
    if(threadIdx.x==0){
        unsigned int gen = *((volatile unsigned int*)&g_gen);
        if(atomicAdd(&g_cnt, 1u) == HCTA-1u){
            g_cnt = 0;
            __threadfence();
            atomicAdd(&g_gen, 1u);
        } else {
            while(*((volatile unsigned int*)&g_gen) == gen) __nanosleep(40);
        }
        __threadfence();
    }
    __syncthreads();
}

// ---- persistent GRU scan v2c: 128 CTAs x 512 thr (16 warps/SM), in-CTA K-reduction ----
// CTA owns 16 hidden cols (48 N-rows); 16 warps split K=2048 into 128-chunks.
// Two-stage smem reduction keeps buffer at 48KB.
__global__ void __launch_bounds__(512, 1) k_scan2(
    const uint32_t* __restrict__ WhiU,
    const float* __restrict__ Gi, const float* __restrict__ bhh,
    const __nv_bfloat16* __restrict__ hzb,
    float* __restrict__ Hall, __nv_bfloat16* __restrict__ Hhi, __nv_bfloat16* __restrict__ Hlo)
{
    __shared__ float sm[8][32][48];   // 48KB
    const int lane = threadIdx.x & 31;
    const int warp = threadIdx.x >> 5;      // 0..15 (K chunk)
    const int gid = lane >> 2, tq = lane & 3;
    const int c = blockIdx.x;
    const int jc = c*16;
    const size_t Ks = Fc;
    const int kw = warp*128;                // warp's K range
    const int T0 = warp*8;                  // warp's first global ktile
    const size_t aoff = (size_t)gid*Ks + tq*2;
    const int slot = warp & 7;

    for(int b=0; b<Bc; b++){
        const __nv_bfloat16* Ahi = b ? (Hhi + (size_t)(b-1)*Tc*Fc) : hzb;
        const __nv_bfloat16* Alo = b ? (Hlo + (size_t)(b-1)*Tc*Fc) : hzb;

        // ---- GEMM: 32 x 48 x 128 per warp, 2-term ----
        float acc[2][6][4];
        #pragma unroll
        for(int mt=0;mt<2;mt++)
            #pragma unroll
            for(int nt=0;nt<6;nt++)
                #pragma unroll
                for(int q=0;q<4;q++) acc[mt][nt][q]=0.f;

        uint32_t ah[2][4], al[2][4], bh[2][6][2];
        {
            const size_t bo = (((size_t)T0*HCTA + c)*6)*64 + lane*2;
            #pragma unroll
            for(int nn=0;nn<6;nn++){
                uint2 u = ldcg_v2(WhiU + bo + nn*64);
                bh[0][nn][0]=u.x; bh[0][nn][1]=u.y;
            }
        }
        int cur = 0;
        #pragma unroll 1
        for(int t=0; t<8; t++){
            if(t+1 < 8){
                const size_t bo = (((size_t)(T0+t+1)*HCTA + c)*6)*64 + lane*2;
                #pragma unroll
                for(int nn=0;nn<6;nn++){
                    uint2 u = ldcg_v2(WhiU + bo + nn*64);
                    bh[cur^1][nn][0]=u.x; bh[cur^1][nn][1]=u.y;
                }
            }
            const int kb = kw + t*16;
            const __nv_bfloat16 *pa = Ahi + aoff + kb;
            const __nv_bfloat16 *qa = Alo + aoff + kb;
            ah[0][0]=ld32(pa);        ah[0][2]=ld32(pa+8);
            ah[0][1]=ld32(pa+8*Ks);   ah[0][3]=ld32(pa+8*Ks+8);
            ah[1][0]=ld32(pa+16*Ks);  ah[1][2]=ld32(pa+16*Ks+8);
            ah[1][1]=ld32(pa+24*Ks);  ah[1][3]=ld32(pa+24*Ks+8);
            al[0][0]=ld32(qa);        al[0][2]=ld32(qa+8);
            al[0][1]=ld32(qa+8*Ks);   al[0][3]=ld32(qa+8*Ks+8);
            al[1][0]=ld32(qa+16*Ks);  al[1][2]=ld32(qa+16*Ks+8);
            al[1][1]=ld32(qa+24*Ks);  al[1][3]=ld32(qa+24*Ks+8);
            #pragma unroll
            for(int nn=0;nn<6;nn++){
                #pragma unroll
                for(int mt=0;mt<2;mt++){
                    mma16816(acc[mt][nn], ah[mt][0],ah[mt][1],ah[mt][2],ah[mt][3], bh[cur][nn][0], bh[cur][nn][1]);
                    mma16816(acc[mt][nn], al[mt][0],al[mt][1],al[mt][2],al[mt][3], bh[cur][nn][0], bh[cur][nn][1]);
                }
            }
            cur ^= 1;
        }

        // ---- two-stage deposit into 8 smem slots ----
        if(warp < 8){
            #pragma unroll
            for(int mt=0;mt<2;mt++){
                #pragma unroll
                for(int nn=0;nn<6;nn++){
                    int row = mt*16 + gid;
                    int col = nn*8 + tq*2;
                    *(float2*)&sm[slot][row][col]   = *(float2*)&acc[mt][nn][0];
                    *(float2*)&sm[slot][row+8][col] = *(float2*)&acc[mt][nn][2];
                }
            }
        }
        __syncthreads();
        if(warp >= 8){
            #pragma unroll
            for(int mt=0;mt<2;mt++){
                #pragma unroll
                for(int nn=0;nn<6;nn++){
                    int row = mt*16 + gid;
                    int col = nn*8 + tq*2;
                    float2 p0 = *(float2*)&sm[slot][row][col];
                    float2 p1 = *(float2*)&sm[slot][row+8][col];
                    p0.x += acc[mt][nn][0]; p0.y += acc[mt][nn][1];
                    p1.x += acc[mt][nn][2]; p1.y += acc[mt][nn][3];
                    *(float2*)&sm[slot][row][col]   = p0;
                    *(float2*)&sm[slot][row+8][col] = p1;
                }
            }
        }
        __syncthreads();

        // ---- reduce over 8 slots + gate; 1 output per thread (512 = 32 rows x 16 cols) ----
        {
            int o = threadIdx.x;
            int row = o >> 4, q = o & 15;
            float gr=0.f, gz=0.f, gn=0.f;
            #pragma unroll
            for(int w=0;w<8;w++){
                gr += sm[w][row][q];
                gz += sm[w][row][16+q];
                gn += sm[w][row][32+q];
            }
            int j = jc + q;
            const float* gi = Gi + ((size_t)b*Tc + row)*G3;
            float r = 1.f/(1.f + expf(-(gi[j]      + gr + bhh[j])));
            float z = 1.f/(1.f + expf(-(gi[2048+j] + gz + bhh[2048+j])));
            float n = tanhf(gi[4096+j] + r*(gn + bhh[4096+j]));
            float hpv = b ? Hall[((size_t)(b-1)*Tc + row)*Fc + j] : 0.f;
            float h = (1.f - z)*n + z*hpv;
            size_t base = ((size_t)b*Tc + row)*Fc + j;
            Hall[base] = h;
            __nv_bfloat16 hh, hl;
            split1(h, hh, hl);
            Hhi[base] = hh;
            Hlo[base] = hl;
        }
        gbar2();
    }
}

// ---- f32 SGEMM (capsule priors only) ----
__global__ void __launch_bounds__(256) k_sgemm(const float* __restrict__ A,
                                               const float* __restrict__ Bm,
                                               const float* __restrict__ bias,
                                               float* __restrict__ C,
                                               int Ncols, int K)
{
    __shared__ float As[8][128];
    __shared__ float Bs[8][128];
    const int tid = threadIdx.x;
    const int tx = tid & 15, ty = tid >> 4;
    const int m0 = blockIdx.y*128, n0 = blockIdx.x*128;
    const int lr = tid >> 1, lc = (tid & 1)*4;
    const float* Ap = A + (size_t)(m0+lr)*K + lc;
    const float* Bp = Bm + (size_t)(n0+lr)*K + lc;

    unsigned long long acc[8][4];
    #pragma unroll
    for(int i=0;i<8;i++)
        #pragma unroll
        for(int j=0;j<4;j++) acc[i][j]=0ULL;

    for(int k0=0;k0<K;k0+=8){
        float4 av = *(const float4*)(Ap + k0);
        float4 bv = *(const float4*)(Bp + k0);
        __syncthreads();
        As[lc+0][lr]=av.x; As[lc+1][lr]=av.y; As[lc+2][lr]=av.z; As[lc+3][lr]=av.w;
        Bs[lc+0][lr]=bv.x; Bs[lc+1][lr]=bv.y; Bs[lc+2][lr]=bv.z; Bs[lc+3][lr]=bv.w;
        __syncthreads();
        #pragma unroll
        for(int k=0;k<8;k++){
            float4 a0 = *(const float4*)&As[k][ty*8];
            float4 a1 = *(const float4*)&As[k][ty*8+4];
            ulonglong2 b01 = *(const ulonglong2*)&Bs[k][tx*8];
            ulonglong2 b23 = *(const ulonglong2*)&Bs[k][tx*8+4];
            unsigned long long aa[8];
            aa[0]=pk2(a0.x); aa[1]=pk2(a0.y); aa[2]=pk2(a0.z); aa[3]=pk2(a0.w);
            aa[4]=pk2(a1.x); aa[5]=pk2(a1.y); aa[6]=pk2(a1.z); aa[7]=pk2(a1.w);
            #pragma unroll
            for(int i=0;i<8;i++){
                ffma2(acc[i][0], aa[i], b01.x);
                ffma2(acc[i][1], aa[i], b01.y);
                ffma2(acc[i][2], aa[i], b23.x);
                ffma2(acc[i][3], aa[i], b23.y);
            }
        }
    }
    #pragma unroll
    for(int i=0;i<8;i++){
        int row = m0 + ty*8 + i;
        #pragma unroll
        for(int j=0;j<4;j++){
            float2 v = up2(acc[i][j]);
            int col = n0 + tx*8 + j*2;
            float b0 = bias ? bias[col]   : 0.f;
            float b1 = bias ? bias[col+1] : 0.f;
            C[(size_t)row*Ncols + col]   = v.x + b0;
            C[(size_t)row*Ncols + col+1] = v.y + b1;
        }
    }
}

// ---- temporal attention ----
__global__ void __launch_bounds__(256) k_attn(const float* __restrict__ Emb,
                                              const float* __restrict__ Aw,
                                              const float* __restrict__ Ab,
                                              float* __restrict__ XN)
{
    __shared__ float sW[32][33];
    __shared__ float sB[32];
    int tid = threadIdx.x;
    for(int i=tid;i<1024;i+=256) sW[i>>5][i&31] = Aw[i];
    if(tid<32) sB[tid]=Ab[tid];
    __syncthreads();
    int g = blockIdx.x*256 + tid;
    int b = g >> 11, f = g & 2047;
    float tA[32];
    #pragma unroll
    for(int t=0;t<32;t++) tA[t] = tanhf(Emb[((size_t)b*32 + t)*Fc + f]);
    float mx = -1e30f, aw[32];
    #pragma unroll
    for(int t2=0;t2<32;t2++){
        float s = sB[t2];
        #pragma unroll
        for(int t=0;t<32;t++) s += tA[t]*sW[t2][t];
        aw[t2]=s; mx = fmaxf(mx, s);
    }
    float den=0.f, num=0.f;
    #pragma unroll
    for(int t=0;t<32;t++){ float e = expf(aw[t]-mx); den += e; num += e*tA[t]; }
    XN[g] = tanhf(num/den);
}

// ---- GAT projections ----
__global__ void __launch_bounds__(256) k_lin64(const float* __restrict__ X,
                                               const float* __restrict__ Wl, const float* __restrict__ bl,
                                               const float* __restrict__ Wr, const float* __restrict__ br,
                                               float* __restrict__ XL, float* __restrict__ XR)
{
    __shared__ float sX[64][65];
    __shared__ float sW[64][65];
    int tid = threadIdx.x;
    int r0 = blockIdx.x*64;
    for(int i=tid;i<4096;i+=256){ int r=i>>6, c=i&63; sX[r][c]=X[(size_t)(r0+r)*64+c]; }
    for(int i=tid;i<4096;i+=256){ int r=i>>6, c=i&63; sW[r][c]=Wl[i]; }
    __syncthreads();
    int r = tid & 63, cq = tid >> 6;
    #pragma unroll 4
    for(int cc=0; cc<16; cc++){
        int c = cq*16 + cc;
        float s = bl[c];
        #pragma unroll
        for(int k=0;k<64;k++) s += sX[r][k]*sW[c][k];
        XL[(size_t)(r0+r)*64 + c] = s;
    }
    __syncthreads();
    for(int i=tid;i<4096;i+=256){ int rr=i>>6, c=i&63; sW[rr][c]=Wr[i]; }
    __syncthreads();
    #pragma unroll 4
    for(int cc=0; cc<16; cc++){
        int c = cq*16 + cc;
        float s = br[c];
        #pragma unroll
        for(int k=0;k<64;k++) s += sX[r][k]*sW[c][k];
        XR[(size_t)(r0+r)*64 + c] = s;
    }
}

// ---- GATv2 dense 32x32 block graph ----
__global__ void __launch_bounds__(128) k_gat(const float* __restrict__ XL,
                                             const float* __restrict__ XR,
                                             const float* __restrict__ att,
                                             const float* __restrict__ bias,
                                             float* __restrict__ OUT)
{
    int w = threadIdx.x >> 5, lane = threadIdx.x & 31;
    int g = blockIdx.x >> 3;
    int d = ((blockIdx.x & 7) << 2) + w;
    int nd = g*32 + d;
    float xr0 = XR[(size_t)nd*64 + lane];
    float xr1 = XR[(size_t)nd*64 + 32 + lane];
    float a0 = att[lane], a1 = att[lane+32];
    const float* xlg = XL + (size_t)g*32*64;
    float lg[32];
    #pragma unroll
    for(int s=0;s<32;s++){
        float u = xlg[s*64 + lane]      + xr0;
        float v = xlg[s*64 + 32 + lane] + xr1;
        u = u>0.f ? u : 0.2f*u;
        v = v>0.f ? v : 0.2f*v;
        float t = u*a0 + v*a1;
        #pragma unroll
        for(int o=16;o>0;o>>=1) t += __shfl_xor_sync(0xffffffffu, t, o);
        lg[s] = t;
    }
    float m = -1e30f;
    #pragma unroll
    for(int s=0;s<32;s++) m = fmaxf(m, lg[s]);
    float den = 0.f;
    #pragma unroll
    for(int s=0;s<32;s++){ lg[s] = expf(lg[s]-m); den += lg[s]; }
    float inv = 1.f/den, o0=0.f, o1=0.f;
    #pragma unroll
    for(int s=0;s<32;s++){
        float al = lg[s]*inv;
        o0 += al * xlg[s*64 + lane];
        o1 += al * xlg[s*64 + 32 + lane];
    }
    OUT[(size_t)nd*64 + lane]      = tanhf(o0 + bias[lane]);
    OUT[(size_t)nd*64 + 32 + lane] = tanhf(o1 + bias[lane+32]);
}

// ---- fusion concat ----
__global__ void k_fus(const float* __restrict__ XN, const float* __restrict__ G0,
                      const float* __restrict__ G1, float* __restrict__ FUS)
{
    int i = blockIdx.x*256 + threadIdx.x;
    int n = i >> 7, q = i & 127;
    FUS[i] = (q < 64) ? XN[(size_t)n*64 + q]
                      : (G0[(size_t)n*64 + q-64] + G1[(size_t)n*64 + q-64]);
}

// ---- capsule routing + head ----
__global__ void __launch_bounds__(64) k_route(const float* __restrict__ PR,
                                              const float* __restrict__ Fw,
                                              const float* __restrict__ Fb,
                                              float* __restrict__ out)
{
    int n = blockIdx.x, l = threadIdx.x;
    const float* base = PR + (size_t)n*65536 + l;
    float o0[32], o1[32], pc[32], te[32];
    #pragma unroll
    for(int o=0;o<32;o++) o0[o]=0.f;
    for(int c=0;c<32;c++){
        const float* pcol = base + (size_t)c*2048;
        #pragma unroll
        for(int o=0;o<32;o++) o0[o] += pcol[o*64];
    }
    #pragma unroll
    for(int o=0;o<32;o++){ o0[o] *= (1.f/32.f); o1[o]=0.f; }
    for(int c=0;c<32;c++){
        const float* pcol = base + (size_t)c*2048;
        float m = -1e30f;
        #pragma unroll
        for(int o=0;o<32;o++){ pc[o]=pcol[o*64]; float lgv = pc[o]*o0[o]; te[o]=lgv; m = fmaxf(m,lgv); }
        float den=0.f;
        #pragma unroll
        for(int o=0;o<32;o++){ te[o]=expf(te[o]-m); den+=te[o]; }
        float inv = 1.f/den;
        #pragma unroll
        for(int o=0;o<32;o++) o1[o] += te[o]*inv*pc[o];
    }
    #pragma unroll
    for(int o=0;o<32;o++){ o0[o] += o1[o]; o1[o]=0.f; }
    for(int c=0;c<32;c++){
        const float* pcol = base + (size_t)c*2048;
        float m = -1e30f;
        #pragma unroll
        for(int o=0;o<32;o++){ pc[o]=pcol[o*64]; float lgv = pc[o]*o0[o]; te[o]=lgv; m = fmaxf(m,lgv); }
        float den=0.f;
        #pragma unroll
        for(int o=0;o<32;o++){ te[o]=expf(te[o]-m); den+=te[o]; }
        float inv = 1.f/den;
        #pragma unroll
        for(int o=0;o<32;o++) o1[o] += te[o]*inv*pc[o];
    }
    __shared__ float sc[32][65];
    #pragma unroll
    for(int o=0;o<32;o++) sc[o][l] = tanhf(o1[o]);
    __syncthreads();
    for(int q=0;q<16;q++){
        int idx = l*16 + q;
        int o = idx >> 5, d2 = idx & 31;
        float s = Fb[d2];
        #pragma unroll
        for(int ll=0;ll<64;ll++) s += sc[o][ll]*Fw[d2*64+ll];
        out[(size_t)n*1024 + o*32 + d2] = tanhf(s);
    }
}

extern "C" void kernel_launch(void* const* d_in, const int* in_sizes, int n_in,
                              void* d_out, int out_size)
{
    const float* inputs = (const float*)d_in[0];
    const float* Wih0 = (const float*)d_in[1];
    const float* Whh0 = (const float*)d_in[2];
    const float* bih0 = (const float*)d_in[3];
    const float* bhh0 = (const float*)d_in[4];
    const float* Wih1 = (const float*)d_in[5];
    const float* Whh1 = (const float*)d_in[6];
    const float* bih1 = (const float*)d_in[7];
    const float* bhh1 = (const float*)d_in[8];
    const float* A_w  = (const float*)d_in[9];
    const float* A_b  = (const float*)d_in[10];
    const float* g0_Wl = (const float*)d_in[11];
    const float* g0_bl = (const float*)d_in[12];
    const float* g0_Wr = (const float*)d_in[13];
    const float* g0_br = (const float*)d_in[14];
    const float* g0_att = (const float*)d_in[15];
    const float* g0_bias = (const float*)d_in[16];
    const float* g1_Wl = (const float*)d_in[17];
    const float* g1_bl = (const float*)d_in[18];
    const float* g1_Wr = (const float*)d_in[19];
    const float* g1_br = (const float*)d_in[20];
    const float* g1_att = (const float*)d_in[21];
    const float* g1_bias = (const float*)d_in[22];
    const float* W_caps = (const float*)d_in[23];
    const float* F_w = (const float*)d_in[24];
    const float* F_b = (const float*)d_in[25];
    float* out = (float*)d_out;

    float *Gi,*H0,*Emb,*XN,*XL,*XR,*G0,*G1,*FUS,*PR;
    __nv_bfloat16 *Xhi,*Xlo,*H0hi,*H0lo,*Ehi,*Elo,*hzb;
    __nv_bfloat16 *Wih0h,*Wih1h;
    uint32_t *Whh0hU,*Whh1hU;
    cudaGetSymbolAddress((void**)&Gi,  g_Gi);
    cudaGetSymbolAddress((void**)&H0,  g_H0);
    cudaGetSymbolAddress((void**)&Emb, g_Emb);
    cudaGetSymbolAddress((void**)&XN,  g_XN);
    cudaGetSymbolAddress((void**)&XL,  g_XL);
    cudaGetSymbolAddress((void**)&XR,  g_XR);
    cudaGetSymbolAddress((void**)&G0,  g_G0);
    cudaGetSymbolAddress((void**)&G1,  g_G1);
    cudaGetSymbolAddress((void**)&FUS, g_FUS);
    cudaGetSymbolAddress((void**)&PR,  g_PR);
    cudaGetSymbolAddress((void**)&Xhi, g_Xhi);  cudaGetSymbolAddress((void**)&Xlo, g_Xlo);
    cudaGetSymbolAddress((void**)&H0hi,g_H0hi); cudaGetSymbolAddress((void**)&H0lo,g_H0lo);
    cudaGetSymbolAddress((void**)&Ehi, g_Ehi);  cudaGetSymbolAddress((void**)&Elo, g_Elo);
    cudaGetSymbolAddress((void**)&hzb, g_hzb);
    cudaGetSymbolAddress((void**)&Wih0h, g_Wih0h);
    cudaGetSymbolAddress((void**)&Wih1h, g_Wih1h);
    cudaGetSymbolAddress((void**)&Whh0hU, g_Whh0h);
    cudaGetSymbolAddress((void**)&Whh1hU, g_Whh1h);

    // launch order (profiler index = mine + 2): 0 prep, 1 mma2, 2 pad, 3 scan2 L0 <- ncu slot 5
    const size_t prep_ctas = (PREP_TOT + 255) / 256;
    k_prep<<<(unsigned)prep_ctas, 256>>>(inputs, Wih0, Wih1, Whh0, Whh1);
    k_mma2<<<dim3(G3/128, (Bc*Tc)/64), 128>>>(Xhi, Xlo, Wih0h, Gi, bih0, Fc, G3);
    k_pad<<<1, 32>>>();
    k_scan2<<<HCTA, 512>>>(Whh0hU, Gi, bhh0, hzb, H0, H0hi, H0lo);
    k_mma2<<<dim3(G3/128, (Bc*Tc)/64), 128>>>(H0hi, H0lo, Wih1h, Gi, bih1, Fc, G3);
    k_scan2<<<HCTA, 512>>>(Whh1hU, Gi, bhh1, hzb, Emb, Ehi, Elo);
    // attention -> node features
    k_attn<<<(Bc*Fc)/256, 256>>>(Emb, A_w, A_b, XN);
    // GAT layers
    k_lin64<<<Nn/64, 256>>>(XN, g0_Wl, g0_bl, g0_Wr, g0_br, XL, XR);
    k_gat<<<1024, 128>>>(XL, XR, g0_att, g0_bias, G0);
    k_lin64<<<Nn/64, 256>>>(G0, g1_Wl, g1_bl, g1_Wr, g1_br, XL, XR);
    k_gat<<<1024, 128>>>(XL, XR, g1_att, g1_bias, G1);
    // fusion + capsule priors
    k_fus<<<(Nn*128)/256, 256>>>(XN, G0, G1, FUS);
    k_sgemm<<<dim3(2048/128, Nn/128), 256>>>(FUS, W_caps, nullptr, PR, 2048, 128);
    // routing + head
    k_route<<<Bc, 64>>>(PR, F_w, F_b, out);
}